// round 15
// baseline (speedup 1.0000x reference)
#include <cuda_runtime.h>
#include <cuda_bf16.h>
#include <cstdint>

// Problem constants (fixed shapes)
#define NN   20000
#define EE   320000
#define ETOT 340000      // EE + NN self-loops
#define DIN  768
#define F1   1024        // H1*C1
#define H1H  8
#define C1C  128
#define F2   128
#define NEG  0.2f
#define BNEPS 1e-5f

#define K1P  (3 * DIN)   // 2304  triple-split K for GEMM1
#define K2P  (3 * F1)    // 3072  triple-split K for GEMM2
#define DCAP 2048        // smem CSR staging cap (max deg ~50 for this graph)

// ---------------- scratch (device globals; no allocation allowed) ----------
__device__ float d_h1[NN * F1];
__device__ float d_g1[NN * F1];
__device__ float d_h2[NN * F2];
__device__ float d_g2[NN * F2];
__device__ float d_as1[NN * H1H];
__device__ float d_ad1[NN * H1H];
__device__ float d_as2[NN];
__device__ float d_ad2[NN];
__device__ int   d_deg[NN];
__device__ int   d_off[NN + 1];
__device__ int   d_cnt[NN];
__device__ int   d_csr[ETOT];
__device__ float d_bsum[F1];
__device__ float d_bsq[F1];
__device__ float d_scale[F1];
__device__ float d_shift[F1];
__device__ int   d_is64;
// split-bf16 operands (words = bf16x2; low half = even k, high = odd k)
__device__ unsigned d_xs [NN * (K1P / 2)];        // A' GEMM1 [row][3K/2 words]
__device__ unsigned d_g1s[NN * (K2P / 2)];        // A' GEMM2
__device__ unsigned d_w1t[F1 * (K1P / 2)];        // B'' GEMM1 [n][3K/2 words]
__device__ unsigned d_w2t[F2 * (K2P / 2)];        // B'' GEMM2

// ---------------- bf16 helpers ----------------------------------------------
__device__ __forceinline__ unsigned packbf(float fhi, float flo) {
    unsigned r;
    asm("cvt.rn.bf16x2.f32 %0, %1, %2;\n" : "=r"(r) : "f"(fhi), "f"(flo));
    return r;
}
__device__ __forceinline__ float bfhi(float v) {
    unsigned r = packbf(v, v);
    return __uint_as_float(r & 0xffff0000u);
}
__device__ __forceinline__ float eluf(float v) {
    return v > 0.f ? v : (__expf(v) - 1.f);
}
__device__ __forceinline__ uint32_t smem_u32(const void* p) {
    uint32_t a;
    asm("{ .reg .u64 t; cvta.to.shared.u64 t, %1; cvt.u32.u64 %0, t; }"
        : "=r"(a) : "l"(p));
    return a;
}
__device__ __forceinline__ void cpasync16(uint32_t smem_dst, const void* gsrc, int srcsize) {
    asm volatile("cp.async.cg.shared.global [%0], [%1], 16, %2;\n"
                 :: "r"(smem_dst), "l"(gsrc), "r"(srcsize));
}
__device__ __forceinline__ uint32_t swz(uint32_t off) {   // SW128 swizzle
    return off ^ ((off >> 3) & 0x70);
}
__device__ __forceinline__ void mma16(float* d, const unsigned* a, const unsigned* b) {
    asm volatile(
        "mma.sync.aligned.m16n8k16.row.col.f32.bf16.bf16.f32 "
        "{%0,%1,%2,%3}, {%4,%5,%6,%7}, {%8,%9}, {%0,%1,%2,%3};\n"
        : "+f"(d[0]), "+f"(d[1]), "+f"(d[2]), "+f"(d[3])
        : "r"(a[0]), "r"(a[1]), "r"(a[2]), "r"(a[3]), "r"(b[0]), "r"(b[1]));
}
__device__ __forceinline__ void ldm4(unsigned* r, uint32_t addr) {
    asm volatile("ldmatrix.sync.aligned.m8n8.x4.shared.b16 {%0,%1,%2,%3}, [%4];"
                 : "=r"(r[0]), "=r"(r[1]), "=r"(r[2]), "=r"(r[3]) : "r"(addr));
}
// online-softmax combine: (m,z) <- (m,z) ⊕ (m2,z2)
__device__ __forceinline__ void oz_comb(float& m, float& z, float m2, float z2) {
    if (m2 > m) { z = z * __expf(m - m2) + z2; m = m2; }
    else        { z = z + z2 * __expf(m2 - m); }
}

// ---------------- dtype detection (parallel) --------------------------------
__global__ void k_detect(const void* ei) {
    __shared__ int ok;
    int t = threadIdx.x;
    if (t == 0) ok = 1;
    __syncthreads();
    long long v = ((const long long*)ei)[t];
    if (v < 0 || v >= NN) ok = 0;
    __syncthreads();
    if (t == 0) d_is64 = ok;
}

__device__ __forceinline__ int load_idx(const void* ei, int i) {
    int v = d_is64 ? (int)((const long long*)ei)[i] : ((const int*)ei)[i];
    v = v < 0 ? 0 : (v >= NN ? NN - 1 : v);
    return v;
}

// ---------------- CSR build ------------------------------------------------
__global__ void k_count(const void* __restrict__ ei) {
    int i = blockIdx.x * blockDim.x + threadIdx.x;
    if (i >= ETOT) return;
    if (i < NN) d_cnt[i] = 0;
    int dst = (i < EE) ? load_idx(ei, EE + i) : (i - EE);
    atomicAdd(&d_deg[dst], 1);
}

__global__ void k_scan() {
    __shared__ int s[1024];
    __shared__ int carry;
    int tid = threadIdx.x;
    if (tid == 0) { carry = 0; d_off[0] = 0; }
    __syncthreads();
    for (int base = 0; base < NN; base += 1024) {
        int i = base + tid;
        int v = (i < NN) ? d_deg[i] : 0;
        s[tid] = v;
        __syncthreads();
        #pragma unroll
        for (int ofs = 1; ofs < 1024; ofs <<= 1) {
            int t = (tid >= ofs) ? s[tid - ofs] : 0;
            __syncthreads();
            s[tid] += t;
            __syncthreads();
        }
        if (i < NN) d_off[i + 1] = carry + s[tid];
        __syncthreads();
        if (tid == 0) carry += s[1023];
        __syncthreads();
    }
}

__global__ void k_scatter(const void* __restrict__ ei) {
    int i = blockIdx.x * blockDim.x + threadIdx.x;
    if (i >= ETOT) return;
    if (i < F1) { d_bsum[i] = 0.f; d_bsq[i] = 0.f; }
    int src, dst;
    if (i < EE) { src = load_idx(ei, i); dst = load_idx(ei, EE + i); }
    else        { src = dst = i - EE; }
    int p = d_off[dst] + atomicAdd(&d_cnt[dst], 1);
    d_csr[p] = src;
}

// ---------------- conversion passes -----------------------------------------
__global__ void conv_x(const float* __restrict__ X) {
    int idx = blockIdx.x * blockDim.x + threadIdx.x;
    if (idx >= NN * (DIN / 2)) return;
    int r = idx / (DIN / 2), kp = idx % (DIN / 2);
    float2 v = *(const float2*)(X + (size_t)r * DIN + 2 * kp);
    float h0 = bfhi(v.x), h1 = bfhi(v.y);
    unsigned hp = packbf(h1, h0);
    unsigned lp = packbf(v.y - h1, v.x - h0);
    unsigned* row = d_xs + (size_t)r * (K1P / 2);
    row[kp] = hp;
    row[DIN / 2 + kp] = lp;
    row[DIN + kp] = hp;
}

__global__ void conv_g1(const float* __restrict__ scale,
                        const float* __restrict__ shift) {
    int idx = blockIdx.x * blockDim.x + threadIdx.x;
    if (idx < F2) { d_bsum[idx] = 0.f; d_bsq[idx] = 0.f; }
    if (idx >= NN * (F1 / 2)) return;
    int r = idx / (F1 / 2), kp = idx % (F1 / 2);
    float2 v = *(const float2*)(d_g1 + (size_t)r * F1 + 2 * kp);
    float2 sc = *(const float2*)(scale + 2 * kp);
    float2 sh = *(const float2*)(shift + 2 * kp);
    float a0 = eluf(v.x * sc.x + sh.x);
    float a1 = eluf(v.y * sc.y + sh.y);
    float h0 = bfhi(a0), h1 = bfhi(a1);
    unsigned hp = packbf(h1, h0);
    unsigned lp = packbf(a1 - h1, a0 - h0);
    unsigned* row = d_g1s + (size_t)r * (K2P / 2);
    row[kp] = hp;
    row[F1 / 2 + kp] = lp;
    row[F1 + kp] = hp;
}

__global__ void conv_wt(const float* __restrict__ W, unsigned* __restrict__ Wt,
                        int K, int N) {
    int idx = blockIdx.x * blockDim.x + threadIdx.x;
    int rowW = 3 * K / 2;
    if (idx >= N * rowW) return;
    int n = idx / rowW, p = idx % rowW;
    int k2 = 2 * p;
    int k; bool lo;
    if (k2 < K)          { k = k2;         lo = false; }
    else if (k2 < 2 * K) { k = k2 - K;     lo = false; }
    else                 { k = k2 - 2 * K; lo = true;  }
    float v0 = W[(size_t)k * N + n];
    float v1 = W[(size_t)(k + 1) * N + n];
    unsigned r;
    if (!lo) r = packbf(bfhi(v1), bfhi(v0));
    else     r = packbf(v1 - bfhi(v1), v0 - bfhi(v0));
    Wt[(size_t)n * rowW + p] = r;
}

// ---------------- split-bf16 HMMA GEMM with ldmatrix -------------------------
#define STG_BYTES 32768
#define GEMM_SMEM (3 * STG_BYTES)            // 98304 bytes

__global__ __launch_bounds__(256)
void gemm_lm(const unsigned* __restrict__ Aw,
             const unsigned* __restrict__ Bw,
             float* __restrict__ C, int M, int N, int Kb,
             const float* __restrict__ att_s, const float* __restrict__ att_d,
             float* __restrict__ das, float* __restrict__ dad, int hstride) {
    extern __shared__ unsigned smw[];
    const uint32_t sb = smem_u32(smw);
    const int tid  = threadIdx.x;
    const int lane = tid & 31;
    const int wid  = tid >> 5;
    const int g = lane >> 2;
    const int c = lane & 3;
    const int warpM = (wid & 1) * 64;
    const int warpN = (wid >> 1) * 32;
    const int blockM = blockIdx.y * 128;
    const int blockN = blockIdx.x * 128;
    const int KbW = Kb >> 1;
    const int T = Kb >> 6;

    float acc[4][4][4];
    #pragma unroll
    for (int mt = 0; mt < 4; mt++)
        #pragma unroll
        for (int nt = 0; nt < 4; nt++)
            #pragma unroll
            for (int i = 0; i < 4; i++) acc[mt][nt][i] = 0.f;

    uint32_t aoff[4], boff[2];
    {
        int mi = lane >> 3, lr = lane & 7;
        #pragma unroll
        for (int mt = 0; mt < 4; mt++) {
            int r = warpM + mt * 16 + (mi & 1) * 8 + lr;
            aoff[mt] = (uint32_t)(r * 128) + ((uint32_t)((mi >> 1) * 16) ^ ((r & 7) << 4));
        }
        #pragma unroll
        for (int p = 0; p < 2; p++) {
            int n = warpN + (2 * p + (mi >> 1)) * 8 + lr;
            boff[p] = 16384u + (uint32_t)(n * 128) + ((uint32_t)((mi & 1) * 16) ^ ((n & 7) << 4));
        }
    }

    auto load_stage = [&](int t, int stg) {
        uint32_t base = sb + stg * STG_BYTES;
        const int k0w = t * 32;
        #pragma unroll
        for (int i = 0; i < 4; i++) {
            int lin = i * 256 + tid;
            int r = lin >> 3, ch = lin & 7;
            int gRow = blockM + r;
            cpasync16(base + swz(r * 128 + ch * 16),
                      Aw + (size_t)gRow * KbW + k0w + ch * 4,
                      (gRow < M) ? 16 : 0);
        }
        #pragma unroll
        for (int i = 0; i < 4; i++) {
            int lin = i * 256 + tid;
            int r = lin >> 3, ch = lin & 7;
            cpasync16(base + 16384 + swz(r * 128 + ch * 16),
                      Bw + (size_t)(blockN + r) * KbW + k0w + ch * 4, 16);
        }
    };

    load_stage(0, 0);
    asm volatile("cp.async.commit_group;\n" ::);
    load_stage(1, 1);
    asm volatile("cp.async.commit_group;\n" ::);

    for (int t = 0; t < T; t++) {
        asm volatile("cp.async.wait_group 1;\n" ::);
        __syncthreads();

        if (t + 2 < T) load_stage(t + 2, (t + 2) % 3);
        asm volatile("cp.async.commit_group;\n" ::);

        const uint32_t stgb = sb + (t % 3) * STG_BYTES;

        #pragma unroll
        for (int ks = 0; ks < 4; ks++) {
            unsigned a[4][4], b[2][4];
            #pragma unroll
            for (int mt = 0; mt < 4; mt++)
                ldm4(a[mt], stgb + (aoff[mt] ^ (ks << 5)));
            #pragma unroll
            for (int p = 0; p < 2; p++)
                ldm4(b[p], stgb + (boff[p] ^ (ks << 5)));
            #pragma unroll
            for (int mt = 0; mt < 4; mt++)
                #pragma unroll
                for (int nt = 0; nt < 4; nt++)
                    mma16(acc[mt][nt], a[mt], &b[nt >> 1][(nt & 1) * 2]);
        }
    }

    // ---- fused attention dots: smem cross-warp reduction, plain store ----
    if (att_s) {
        __syncthreads();
        float* sred = (float*)smw;
        sred[tid] = 0.f;
        __syncthreads();
        float asv[8], adv[8];
        #pragma unroll
        for (int nt = 0; nt < 4; nt++) {
            int colg = blockN + warpN + nt * 8 + 2 * c;
            asv[nt * 2]     = att_s[colg];
            asv[nt * 2 + 1] = att_s[colg + 1];
            adv[nt * 2]     = att_d[colg];
            adv[nt * 2 + 1] = att_d[colg + 1];
        }
        #pragma unroll
        for (int mt = 0; mt < 4; mt++) {
            float s0 = 0.f, d0 = 0.f, s1 = 0.f, d1 = 0.f;
            #pragma unroll
            for (int nt = 0; nt < 4; nt++) {
                s0 += acc[mt][nt][0] * asv[nt * 2] + acc[mt][nt][1] * asv[nt * 2 + 1];
                d0 += acc[mt][nt][0] * adv[nt * 2] + acc[mt][nt][1] * adv[nt * 2 + 1];
                s1 += acc[mt][nt][2] * asv[nt * 2] + acc[mt][nt][3] * asv[nt * 2 + 1];
                d1 += acc[mt][nt][2] * adv[nt * 2] + acc[mt][nt][3] * adv[nt * 2 + 1];
            }
            #pragma unroll
            for (int o = 1; o <= 2; o <<= 1) {
                s0 += __shfl_xor_sync(0xffffffffu, s0, o);
                d0 += __shfl_xor_sync(0xffffffffu, d0, o);
                s1 += __shfl_xor_sync(0xffffffffu, s1, o);
                d1 += __shfl_xor_sync(0xffffffffu, d1, o);
            }
            if (c == 0) {
                int r0 = warpM + mt * 16 + g;
                atomicAdd(&sred[r0 * 2],           s0);
                atomicAdd(&sred[r0 * 2 + 1],       d0);
                atomicAdd(&sred[(r0 + 8) * 2],     s1);
                atomicAdd(&sred[(r0 + 8) * 2 + 1], d1);
            }
        }
        __syncthreads();
        if (tid < 128) {
            int row = blockM + tid;
            if (row < M) {
                das[row * hstride + blockIdx.x] = sred[tid * 2];
                dad[row * hstride + blockIdx.x] = sred[tid * 2 + 1];
            }
        }
    }

    // ---- store C ----
    #pragma unroll
    for (int mt = 0; mt < 4; mt++)
        #pragma unroll
        for (int nt = 0; nt < 4; nt++) {
            int row0 = blockM + warpM + mt * 16 + g;
            int col  = blockN + warpN + nt * 8 + 2 * c;
            if (row0 < M)
                *(float2*)(C + (size_t)row0 * N + col) =
                    make_float2(acc[mt][nt][0], acc[mt][nt][1]);
            int row1 = row0 + 8;
            if (row1 < M)
                *(float2*)(C + (size_t)row1 * N + col) =
                    make_float2(acc[mt][nt][2], acc[mt][nt][3]);
        }
}

// ---------------- GAT aggregation (online softmax, smem CSR, unroll 4) -----
__global__ __launch_bounds__(256)
void k_agg1(const float* __restrict__ bias) {
    int n = blockIdx.x;
    int s0 = d_off[n];
    int deg = d_off[n + 1] - s0;
    __shared__ int scsr[DCAP];
    __shared__ float sad[H1H], sm[H1H], sz[H1H];
    __shared__ float pm[256], pz[256];
    int tid = threadIdx.x;
    if (tid < H1H) sad[tid] = d_ad1[n * H1H + tid];
    bool fits = (deg <= DCAP);
    for (int e = tid; e < deg && e < DCAP; e += 256) scsr[e] = d_csr[s0 + e];
    __syncthreads();

    // single online pass: thread handles fixed head (tid&7) across edges
    int h1_ = tid & 7;
    float adv = sad[h1_];
    float lm = -1e30f, lz = 0.f;
    for (int idx = tid; idx < deg * H1H; idx += 256) {
        int e = idx >> 3;
        int src = (fits || e < DCAP) ? scsr[e] : d_csr[s0 + e];
        float v = d_as1[src * H1H + h1_] + adv;
        v = v > 0.f ? v : NEG * v;
        if (v > lm) { lz *= __expf(lm - v); lm = v; }
        lz += __expf(v - lm);
    }
    pm[tid] = lm; pz[tid] = lz;
    __syncthreads();
    if (tid < H1H) {
        float m = -1e30f, z = 0.f;
        for (int j = tid; j < 256; j += H1H) oz_comb(m, z, pm[j], pz[j]);
        sm[tid] = m; sz[tid] = z;
    }
    __syncthreads();

    // weighted gather, 4-edge unrolled (MLP 4)
    int c0 = tid * 4;
    int hh = tid >> 5;
    float m = sm[hh], invz = 1.f / sz[hh], ad = sad[hh];
    float4 acc = make_float4(0.f, 0.f, 0.f, 0.f);
    int e = 0;
    if (fits) {
        for (; e + 4 <= deg; e += 4) {
            int sa = scsr[e], sb2 = scsr[e + 1], sc = scsr[e + 2], sd = scsr[e + 3];
            float va = d_as1[sa * H1H + hh] + ad;
            float vb = d_as1[sb2 * H1H + hh] + ad;
            float vc = d_as1[sc * H1H + hh] + ad;
            float vd = d_as1[sd * H1H + hh] + ad;
            va = va > 0.f ? va : NEG * va;
            vb = vb > 0.f ? vb : NEG * vb;
            vc = vc > 0.f ? vc : NEG * vc;
            vd = vd > 0.f ? vd : NEG * vd;
            float4 ha = *(const float4*)(d_h1 + (size_t)sa * F1 + c0);
            float4 hb = *(const float4*)(d_h1 + (size_t)sb2 * F1 + c0);
            float4 hc = *(const float4*)(d_h1 + (size_t)sc * F1 + c0);
            float4 hd = *(const float4*)(d_h1 + (size_t)sd * F1 + c0);
            float aa = __expf(va - m) * invz;
            float ab = __expf(vb - m) * invz;
            float ac = __expf(vc - m) * invz;
            float adw = __expf(vd - m) * invz;
            acc.x += aa * ha.x + ab * hb.x + ac * hc.x + adw * hd.x;
            acc.y += aa * ha.y + ab * hb.y + ac * hc.y + adw * hd.y;
            acc.z += aa * ha.z + ab * hb.z + ac * hc.z + adw * hd.z;
            acc.w += aa * ha.w + ab * hb.w + ac * hc.w + adw * hd.w;
        }
    }
    for (; e < deg; e++) {
        int src = (fits || e < DCAP) ? scsr[e] : d_csr[s0 + e];
        float v = d_as1[src * H1H + hh] + ad;
        v = v > 0.f ? v : NEG * v;
        float al = __expf(v - m) * invz;
        float4 hv = *(const float4*)(d_h1 + (size_t)src * F1 + c0);
        acc.x += al * hv.x; acc.y += al * hv.y;
        acc.z += al * hv.z; acc.w += al * hv.w;
    }
    float4 bb = *(const float4*)(bias + c0);
    acc.x += bb.x; acc.y += bb.y; acc.z += bb.z; acc.w += bb.w;
    *(float4*)(d_g1 + (size_t)n * F1 + c0) = acc;
}

__global__ __launch_bounds__(128)
void k_agg2(const float* __restrict__ bias) {
    int n = blockIdx.x;
    int s0 = d_off[n];
    int deg = d_off[n + 1] - s0;
    __shared__ int scsr[DCAP];
    __shared__ float wm[4], wz[4], smv, szv;
    int tid = threadIdx.x;
    bool fits = (deg <= DCAP);
    for (int e = tid; e < deg && e < DCAP; e += 128) scsr[e] = d_csr[s0 + e];
    __syncthreads();
    float ad = d_ad2[n];

    float lm = -1e30f, lz = 0.f;
    for (int e = tid; e < deg; e += 128) {
        int src = (fits || e < DCAP) ? scsr[e] : d_csr[s0 + e];
        float v = d_as2[src] + ad;
        v = v > 0.f ? v : NEG * v;
        if (v > lm) { lz *= __expf(lm - v); lm = v; }
        lz += __expf(v - lm);
    }
    #pragma unroll
    for (int o = 16; o; o >>= 1) {
        float m2 = __shfl_xor_sync(0xffffffffu, lm, o);
        float z2 = __shfl_xor_sync(0xffffffffu, lz, o);
        oz_comb(lm, lz, m2, z2);
    }
    if ((tid & 31) == 0) { wm[tid >> 5] = lm; wz[tid >> 5] = lz; }
    __syncthreads();
    if (tid == 0) {
        float m = wm[0], z = wz[0];
        oz_comb(m, z, wm[1], wz[1]);
        oz_comb(m, z, wm[2], wz[2]);
        oz_comb(m, z, wm[3], wz[3]);
        smv = m; szv = z;
    }
    __syncthreads();
    float m = smv, invz = 1.f / szv;

    float acc = 0.f;
    int e = 0;
    if (fits) {
        for (; e + 4 <= deg; e += 4) {
            int sa = scsr[e], sb2 = scsr[e + 1], sc = scsr[e + 2], sd = scsr[e + 3];
            float va = d_as2[sa] + ad, vb = d_as2[sb2] + ad;
            float vc = d_as2[sc] + ad, vd = d_as2[sd] + ad;
            va = va > 0.f ? va : NEG * va;
            vb = vb > 0.f ? vb : NEG * vb;
            vc = vc > 0.f ? vc : NEG * vc;
            vd = vd > 0.f ? vd : NEG * vd;
            float ha = d_h2[(size_t)sa * F2 + tid];
            float hb = d_h2[(size_t)sb2 * F2 + tid];
            float hc = d_h2[(size_t)sc * F2 + tid];
            float hd = d_h2[(size_t)sd * F2 + tid];
            acc += __expf(va - m) * invz * ha + __expf(vb - m) * invz * hb
                 + __expf(vc - m) * invz * hc + __expf(vd - m) * invz * hd;
        }
    }
    for (; e < deg; e++) {
        int src = (fits || e < DCAP) ? scsr[e] : d_csr[s0 + e];
        float v = d_as2[src] + ad;
        v = v > 0.f ? v : NEG * v;
        acc += __expf(v - m) * invz * d_h2[(size_t)src * F2 + tid];
    }
    d_g2[(size_t)n * F2 + tid] = acc + bias[tid];
}

// ---------------- BatchNorm ------------------------------------------------
__global__ void bn_stats(const float* __restrict__ x, float* __restrict__ sum,
                         float* __restrict__ sq, int F) {
    int col = blockIdx.x * 128 + threadIdx.x;
    float s = 0.f, q = 0.f;
    for (int r = blockIdx.y; r < NN; r += gridDim.y) {
        float v = x[(size_t)r * F + col];
        s += v; q += v * v;
    }
    atomicAdd(&sum[col], s);
    atomicAdd(&sq[col], q);
}

__global__ void bn_final(const float* __restrict__ sum, const float* __restrict__ sq,
                         const float* __restrict__ gamma, const float* __restrict__ beta,
                         float* __restrict__ scale, float* __restrict__ shift, int F) {
    int c = blockIdx.x * blockDim.x + threadIdx.x;
    if (c < F) {
        float mu  = sum[c] * (1.f / NN);
        float var = sq[c] * (1.f / NN) - mu * mu;
        float sc  = gamma[c] * rsqrtf(var + BNEPS);
        scale[c] = sc;
        shift[c] = beta[c] - mu * sc;
    }
}

// ---------------- classifier head (fused BN2+ELU, 4 nodes/block) ------------
__global__ __launch_bounds__(256)
void k_classifier(const float* __restrict__ g2, const float* __restrict__ scale,
                  const float* __restrict__ shift,
                  const float* __restrict__ Wc1, const float* __restrict__ bc1,
                  const float* __restrict__ Wc2, const float* __restrict__ bc2,
                  float* __restrict__ out) {
    int sg = threadIdx.x >> 6;
    int t  = threadIdx.x & 63;
    int n  = blockIdx.x * 4 + sg;
    __shared__ float sx[4][128], sh[4][64];
    float v0 = g2[(size_t)n * F2 + t]      * scale[t]      + shift[t];
    float v1 = g2[(size_t)n * F2 + 64 + t] * scale[t + 64] + shift[t + 64];
    sx[sg][t]      = eluf(v0);
    sx[sg][t + 64] = eluf(v1);
    __syncthreads();
    float s = bc1[t];
    #pragma unroll 8
    for (int k = 0; k < 128; k++) s += sx[sg][k] * Wc1[k * 64 + t];
    sh[sg][t] = fmaxf(s, 0.f);
    __syncthreads();
    if (t < 2) {
        float o = bc2[t];
        #pragma unroll 8
        for (int k = 0; k < 64; k++) o += sh[sg][k] * Wc2[k * 2 + t];
        out[n * 2 + t] = o;
    }
}

// ---------------- launch ----------------------------------------------------
extern "C" void kernel_launch(void* const* d_in, const int* in_sizes, int n_in,
                              void* d_out, int out_size) {
    const float* x     = (const float*)d_in[0];
    const void*  ei    = d_in[1];
    const float* W1    = (const float*)d_in[2];
    const float* atts1 = (const float*)d_in[3];
    const float* attd1 = (const float*)d_in[4];
    const float* b1    = (const float*)d_in[5];
    const float* W2    = (const float*)d_in[6];
    const float* atts2 = (const float*)d_in[7];
    const float* attd2 = (const float*)d_in[8];
    const float* b2    = (const float*)d_in[9];
    const float* g1    = (const float*)d_in[10];
    const float* be1   = (const float*)d_in[11];
    const float* g2w   = (const float*)d_in[12];
    const float* be2   = (const float*)d_in[13];
    const float* Wc1   = (const float*)d_in[14];
    const float* bc1   = (const float*)d_in[15];
    const float* Wc2   = (const float*)d_in[16];
    const float* bc2   = (const float*)d_in[17];
    float*       out   = (float*)d_out;

    void *p_deg, *p_h1, *p_g2, *p_bsum, *p_bsq, *p_scale, *p_shift;
    void *p_as1, *p_ad1, *p_as2, *p_ad2, *p_h2, *p_g1;
    void *p_xs, *p_g1s, *p_w1t, *p_w2t;
    cudaGetSymbolAddress(&p_deg,   d_deg);
    cudaGetSymbolAddress(&p_h1,    d_h1);
    cudaGetSymbolAddress(&p_g1,    d_g1);
    cudaGetSymbolAddress(&p_h2,    d_h2);
    cudaGetSymbolAddress(&p_g2,    d_g2);
    cudaGetSymbolAddress(&p_bsum,  d_bsum);
    cudaGetSymbolAddress(&p_bsq,   d_bsq);
    cudaGetSymbolAddress(&p_scale, d_scale);
    cudaGetSymbolAddress(&p_shift, d_shift);
    cudaGetSymbolAddress(&p_as1,   d_as1);
    cudaGetSymbolAddress(&p_ad1,   d_ad1);
    cudaGetSymbolAddress(&p_as2,   d_as2);
    cudaGetSymbolAddress(&p_ad2,   d_ad2);
    cudaGetSymbolAddress(&p_xs,    d_xs);
    cudaGetSymbolAddress(&p_g1s,   d_g1s);
    cudaGetSymbolAddress(&p_w1t,   d_w1t);
    cudaGetSymbolAddress(&p_w2t,   d_w2t);

    cudaFuncSetAttribute(gemm_lm, cudaFuncAttributeMaxDynamicSharedMemorySize,
                         GEMM_SMEM);

    // conversions + CSR build (gemm1 is launch #5 incl. memset for ncu)
    conv_x<<<(NN * (DIN / 2) + 255) / 256, 256>>>(x);                      // 1
    conv_wt<<<(F1 * (K1P / 2) + 255) / 256, 256>>>(W1, (unsigned*)p_w1t, DIN, F1); // 2
    conv_wt<<<(F2 * (K2P / 2) + 255) / 256, 256>>>(W2, (unsigned*)p_w2t, F1, F2);  // 3
    cudaMemsetAsync(p_deg, 0, NN * sizeof(int));                            // 4

    // ---- GAT layer 1: split-bf16 HMMA GEMM (fused attention dots) ----
    {
        dim3 grid(F1 / 128, (NN + 127) / 128);
        gemm_lm<<<grid, 256, GEMM_SMEM>>>((const unsigned*)p_xs,            // 5
                                          (const unsigned*)p_w1t,
                                          (float*)p_h1, NN, F1, K1P,
                                          atts1, attd1,
                                          (float*)p_as1, (float*)p_ad1, H1H);
    }

    k_detect<<<1, 64>>>(ei);
    k_count<<<(ETOT + 255) / 256, 256>>>(ei);
    k_scan<<<1, 1024>>>();
    k_scatter<<<(ETOT + 255) / 256, 256>>>(ei);   // also zeroes BN1 accumulators

    k_agg1<<<NN, 256>>>(b1);

    // BN1 stats -> conv_g1 applies BN+ELU, writes split A', zeroes BN2 accs
    {
        dim3 grid(F1 / 128, 128);
        bn_stats<<<grid, 128>>>((const float*)p_g1, (float*)p_bsum, (float*)p_bsq, F1);
    }
    bn_final<<<F1 / 128, 128>>>((const float*)p_bsum, (const float*)p_bsq, g1, be1,
                                (float*)p_scale, (float*)p_shift, F1);
    conv_g1<<<(NN * (F1 / 2) + 255) / 256, 256>>>((const float*)p_scale,
                                                  (const float*)p_shift);

    // ---- GAT layer 2: split-bf16 HMMA GEMM (fused attention dots) ----
    {
        dim3 grid(1, (NN + 127) / 128);
        gemm_lm<<<grid, 256, GEMM_SMEM>>>((const unsigned*)p_g1s,
                                          (const unsigned*)p_w2t,
                                          (float*)p_h2, NN, F2, K2P,
                                          atts2, attd2,
                                          (float*)p_as2, (float*)p_ad2, 1);
    }
    k_agg2<<<NN, 128>>>(b2);

    // BN2 stats (apply fused into classifier)
    {
        dim3 grid(F2 / 128, 128);
        bn_stats<<<grid, 128>>>((const float*)p_g2, (float*)p_bsum, (float*)p_bsq, F2);
    }
    bn_final<<<1, 128>>>((const float*)p_bsum, (const float*)p_bsq, g2w, be2,
                         (float*)p_scale, (float*)p_shift, F2);

    // ---- classifier head (fused BN2+ELU, 4 nodes/block) ----
    k_classifier<<<NN / 4, 256>>>((const float*)p_g2, (const float*)p_scale,
                                  (const float*)p_shift, Wc1, bc1, Wc2, bc2, out);
}

// round 17
// speedup vs baseline: 1.0583x; 1.0583x over previous
#include <cuda_runtime.h>
#include <cuda_bf16.h>
#include <cstdint>

// Problem constants (fixed shapes)
#define NN   20000
#define EE   320000
#define ETOT 340000      // EE + NN self-loops
#define DIN  768
#define F1   1024        // H1*C1
#define H1H  8
#define C1C  128
#define F2   128
#define NEG  0.2f
#define BNEPS 1e-5f

#define K1P  (3 * DIN)   // 2304  triple-split K for GEMM1
#define K2P  (3 * F1)    // 3072  triple-split K for GEMM2

// ---------------- scratch (device globals; no allocation allowed) ----------
__device__ float d_h1[NN * F1];
__device__ float d_g1[NN * F1];
__device__ float d_h2[NN * F2];
__device__ float d_g2[NN * F2];
__device__ float d_as1[NN * H1H];
__device__ float d_ad1[NN * H1H];
__device__ float d_as2[NN];
__device__ float d_ad2[NN];
__device__ int   d_deg[NN];
__device__ int   d_off[NN + 1];
__device__ int   d_cnt[NN];
__device__ int   d_csr[ETOT];
__device__ float d_bsum[F1];
__device__ float d_bsq[F1];
__device__ float d_scale[F1];
__device__ float d_shift[F1];
__device__ int   d_is64;
// split-bf16 operands (words = bf16x2; low half = even k, high = odd k)
__device__ unsigned d_xs [NN * (K1P / 2)];        // A' GEMM1 [row][3K/2 words]
__device__ unsigned d_g1s[NN * (K2P / 2)];        // A' GEMM2
__device__ unsigned d_w1t[F1 * (K1P / 2)];        // B'' GEMM1 [n][3K/2 words]
__device__ unsigned d_w2t[F2 * (K2P / 2)];        // B'' GEMM2

// ---------------- bf16 helpers ----------------------------------------------
__device__ __forceinline__ unsigned packbf(float fhi, float flo) {
    unsigned r;
    asm("cvt.rn.bf16x2.f32 %0, %1, %2;\n" : "=r"(r) : "f"(fhi), "f"(flo));
    return r;
}
__device__ __forceinline__ float bfhi(float v) {
    unsigned r = packbf(v, v);
    return __uint_as_float(r & 0xffff0000u);
}
__device__ __forceinline__ float eluf(float v) {
    return v > 0.f ? v : (__expf(v) - 1.f);
}
__device__ __forceinline__ uint32_t smem_u32(const void* p) {
    uint32_t a;
    asm("{ .reg .u64 t; cvta.to.shared.u64 t, %1; cvt.u32.u64 %0, t; }"
        : "=r"(a) : "l"(p));
    return a;
}
__device__ __forceinline__ void cpasync16(uint32_t smem_dst, const void* gsrc, int srcsize) {
    asm volatile("cp.async.cg.shared.global [%0], [%1], 16, %2;\n"
                 :: "r"(smem_dst), "l"(gsrc), "r"(srcsize));
}
__device__ __forceinline__ uint32_t swz(uint32_t off) {   // SW128 swizzle
    return off ^ ((off >> 3) & 0x70);
}
__device__ __forceinline__ void mma16(float* d, const unsigned* a, const unsigned* b) {
    asm volatile(
        "mma.sync.aligned.m16n8k16.row.col.f32.bf16.bf16.f32 "
        "{%0,%1,%2,%3}, {%4,%5,%6,%7}, {%8,%9}, {%0,%1,%2,%3};\n"
        : "+f"(d[0]), "+f"(d[1]), "+f"(d[2]), "+f"(d[3])
        : "r"(a[0]), "r"(a[1]), "r"(a[2]), "r"(a[3]), "r"(b[0]), "r"(b[1]));
}
__device__ __forceinline__ void ldm4(unsigned* r, uint32_t addr) {
    asm volatile("ldmatrix.sync.aligned.m8n8.x4.shared.b16 {%0,%1,%2,%3}, [%4];"
                 : "=r"(r[0]), "=r"(r[1]), "=r"(r[2]), "=r"(r[3]) : "r"(addr));
}

// ---------------- dtype detection (parallel) --------------------------------
__global__ void k_detect(const void* ei) {
    __shared__ int ok;
    int t = threadIdx.x;
    if (t == 0) ok = 1;
    __syncthreads();
    long long v = ((const long long*)ei)[t];
    if (v < 0 || v >= NN) ok = 0;
    __syncthreads();
    if (t == 0) d_is64 = ok;
}

__device__ __forceinline__ int load_idx(const void* ei, int i) {
    int v = d_is64 ? (int)((const long long*)ei)[i] : ((const int*)ei)[i];
    v = v < 0 ? 0 : (v >= NN ? NN - 1 : v);
    return v;
}

// ---------------- CSR build ------------------------------------------------
__global__ void k_count(const void* __restrict__ ei) {
    int i = blockIdx.x * blockDim.x + threadIdx.x;
    if (i >= ETOT) return;
    if (i < NN) d_cnt[i] = 0;
    int dst = (i < EE) ? load_idx(ei, EE + i) : (i - EE);
    atomicAdd(&d_deg[dst], 1);
}

__global__ void k_scan() {
    __shared__ int s[1024];
    __shared__ int carry;
    int tid = threadIdx.x;
    if (tid == 0) { carry = 0; d_off[0] = 0; }
    __syncthreads();
    for (int base = 0; base < NN; base += 1024) {
        int i = base + tid;
        int v = (i < NN) ? d_deg[i] : 0;
        s[tid] = v;
        __syncthreads();
        #pragma unroll
        for (int ofs = 1; ofs < 1024; ofs <<= 1) {
            int t = (tid >= ofs) ? s[tid - ofs] : 0;
            __syncthreads();
            s[tid] += t;
            __syncthreads();
        }
        if (i < NN) d_off[i + 1] = carry + s[tid];
        __syncthreads();
        if (tid == 0) carry += s[1023];
        __syncthreads();
    }
}

__global__ void k_scatter(const void* __restrict__ ei) {
    int i = blockIdx.x * blockDim.x + threadIdx.x;
    if (i >= ETOT) return;
    if (i < F1) { d_bsum[i] = 0.f; d_bsq[i] = 0.f; }
    int src, dst;
    if (i < EE) { src = load_idx(ei, i); dst = load_idx(ei, EE + i); }
    else        { src = dst = i - EE; }
    int p = d_off[dst] + atomicAdd(&d_cnt[dst], 1);
    d_csr[p] = src;
}

// ---------------- conversion passes -----------------------------------------
__global__ void conv_x(const float* __restrict__ X) {
    int idx = blockIdx.x * blockDim.x + threadIdx.x;
    if (idx >= NN * (DIN / 2)) return;
    int r = idx / (DIN / 2), kp = idx % (DIN / 2);
    float2 v = *(const float2*)(X + (size_t)r * DIN + 2 * kp);
    float h0 = bfhi(v.x), h1 = bfhi(v.y);
    unsigned hp = packbf(h1, h0);
    unsigned lp = packbf(v.y - h1, v.x - h0);
    unsigned* row = d_xs + (size_t)r * (K1P / 2);
    row[kp] = hp;
    row[DIN / 2 + kp] = lp;
    row[DIN + kp] = hp;
}

__global__ void conv_g1(const float* __restrict__ scale,
                        const float* __restrict__ shift) {
    int idx = blockIdx.x * blockDim.x + threadIdx.x;
    if (idx < F2) { d_bsum[idx] = 0.f; d_bsq[idx] = 0.f; }
    if (idx >= NN * (F1 / 2)) return;
    int r = idx / (F1 / 2), kp = idx % (F1 / 2);
    float2 v = *(const float2*)(d_g1 + (size_t)r * F1 + 2 * kp);
    float2 sc = *(const float2*)(scale + 2 * kp);
    float2 sh = *(const float2*)(shift + 2 * kp);
    float a0 = eluf(v.x * sc.x + sh.x);
    float a1 = eluf(v.y * sc.y + sh.y);
    float h0 = bfhi(a0), h1 = bfhi(a1);
    unsigned hp = packbf(h1, h0);
    unsigned lp = packbf(a1 - h1, a0 - h0);
    unsigned* row = d_g1s + (size_t)r * (K2P / 2);
    row[kp] = hp;
    row[F1 / 2 + kp] = lp;
    row[F1 + kp] = hp;
}

__global__ void conv_wt(const float* __restrict__ W, unsigned* __restrict__ Wt,
                        int K, int N) {
    int idx = blockIdx.x * blockDim.x + threadIdx.x;
    int rowW = 3 * K / 2;
    if (idx >= N * rowW) return;
    int n = idx / rowW, p = idx % rowW;
    int k2 = 2 * p;
    int k; bool lo;
    if (k2 < K)          { k = k2;         lo = false; }
    else if (k2 < 2 * K) { k = k2 - K;     lo = false; }
    else                 { k = k2 - 2 * K; lo = true;  }
    float v0 = W[(size_t)k * N + n];
    float v1 = W[(size_t)(k + 1) * N + n];
    unsigned r;
    if (!lo) r = packbf(bfhi(v1), bfhi(v0));
    else     r = packbf(v1 - bfhi(v1), v0 - bfhi(v0));
    Wt[(size_t)n * rowW + p] = r;
}

// ---------------- split-bf16 HMMA GEMM with ldmatrix -------------------------
// Template MT: block covers 32*MT rows (MT=4 -> 128, MT=2 -> 64). N-tile 128.
template <int MT>
__global__ __launch_bounds__(256)
void gemm_lm(const unsigned* __restrict__ Aw,
             const unsigned* __restrict__ Bw,
             float* __restrict__ C, int M, int N, int Kb,
             const float* __restrict__ att_s, const float* __restrict__ att_d,
             float* __restrict__ das, float* __restrict__ dad, int hstride) {
    constexpr int ROWS  = 32 * MT;
    constexpr int ASTG  = ROWS * 128;            // A stage bytes
    constexpr int STG   = ASTG + 16384;          // + B stage bytes
    extern __shared__ unsigned smw[];
    const uint32_t sb = smem_u32(smw);
    const int tid  = threadIdx.x;
    const int lane = tid & 31;
    const int wid  = tid >> 5;
    const int g = lane >> 2;
    const int c = lane & 3;
    const int warpM = (wid & 1) * (MT * 16);
    const int warpN = (wid >> 1) * 32;
    const int blockM = blockIdx.y * ROWS;
    const int blockN = blockIdx.x * 128;
    const int KbW = Kb >> 1;
    const int T = Kb >> 6;

    float acc[MT][4][4];
    #pragma unroll
    for (int mt = 0; mt < MT; mt++)
        #pragma unroll
        for (int nt = 0; nt < 4; nt++)
            #pragma unroll
            for (int i = 0; i < 4; i++) acc[mt][nt][i] = 0.f;

    uint32_t aoff[MT], boff[2];
    {
        int mi = lane >> 3, lr = lane & 7;
        #pragma unroll
        for (int mt = 0; mt < MT; mt++) {
            int r = warpM + mt * 16 + (mi & 1) * 8 + lr;
            aoff[mt] = (uint32_t)(r * 128) + ((uint32_t)((mi >> 1) * 16) ^ ((r & 7) << 4));
        }
        #pragma unroll
        for (int p = 0; p < 2; p++) {
            int n = warpN + (2 * p + (mi >> 1)) * 8 + lr;
            boff[p] = (uint32_t)ASTG + (uint32_t)(n * 128) + ((uint32_t)((mi & 1) * 16) ^ ((n & 7) << 4));
        }
    }

    auto load_stage = [&](int t, int stg) {
        uint32_t base = sb + stg * STG;
        const int k0w = t * 32;
        #pragma unroll
        for (int i = 0; i < MT; i++) {               // A: ROWS x 8 chunks
            int lin = i * 256 + tid;
            int r = lin >> 3, ch = lin & 7;
            int gRow = blockM + r;
            cpasync16(base + swz(r * 128 + ch * 16),
                      Aw + (size_t)gRow * KbW + k0w + ch * 4,
                      (gRow < M) ? 16 : 0);
        }
        #pragma unroll
        for (int i = 0; i < 4; i++) {                // B: 128 x 8 chunks
            int lin = i * 256 + tid;
            int r = lin >> 3, ch = lin & 7;
            cpasync16(base + ASTG + swz(r * 128 + ch * 16),
                      Bw + (size_t)(blockN + r) * KbW + k0w + ch * 4, 16);
        }
    };

    load_stage(0, 0);
    asm volatile("cp.async.commit_group;\n" ::);
    load_stage(1, 1);
    asm volatile("cp.async.commit_group;\n" ::);

    for (int t = 0; t < T; t++) {
        asm volatile("cp.async.wait_group 1;\n" ::);
        __syncthreads();

        if (t + 2 < T) load_stage(t + 2, (t + 2) % 3);
        asm volatile("cp.async.commit_group;\n" ::);

        const uint32_t stgb = sb + (t % 3) * STG;

        #pragma unroll
        for (int ks = 0; ks < 4; ks++) {
            unsigned a[MT][4], b[2][4];
            #pragma unroll
            for (int mt = 0; mt < MT; mt++)
                ldm4(a[mt], stgb + (aoff[mt] ^ (ks << 5)));
            #pragma unroll
            for (int p = 0; p < 2; p++)
                ldm4(b[p], stgb + (boff[p] ^ (ks << 5)));
            #pragma unroll
            for (int mt = 0; mt < MT; mt++)
                #pragma unroll
                for (int nt = 0; nt < 4; nt++)
                    mma16(acc[mt][nt], a[mt], &b[nt >> 1][(nt & 1) * 2]);
        }
    }

    // ---- fused attention dots: smem cross-warp reduction, plain store ----
    if (att_s) {
        __syncthreads();
        float* sred = (float*)smw;             // [ROWS][2]
        if (tid < 2 * ROWS) sred[tid] = 0.f;
        __syncthreads();
        float asv[8], adv[8];
        #pragma unroll
        for (int nt = 0; nt < 4; nt++) {
            int colg = blockN + warpN + nt * 8 + 2 * c;
            asv[nt * 2]     = att_s[colg];
            asv[nt * 2 + 1] = att_s[colg + 1];
            adv[nt * 2]     = att_d[colg];
            adv[nt * 2 + 1] = att_d[colg + 1];
        }
        #pragma unroll
        for (int mt = 0; mt < MT; mt++) {
            float s0 = 0.f, d0 = 0.f, s1 = 0.f, d1 = 0.f;
            #pragma unroll
            for (int nt = 0; nt < 4; nt++) {
                s0 += acc[mt][nt][0] * asv[nt * 2] + acc[mt][nt][1] * asv[nt * 2 + 1];
                d0 += acc[mt][nt][0] * adv[nt * 2] + acc[mt][nt][1] * adv[nt * 2 + 1];
                s1 += acc[mt][nt][2] * asv[nt * 2] + acc[mt][nt][3] * asv[nt * 2 + 1];
                d1 += acc[mt][nt][2] * adv[nt * 2] + acc[mt][nt][3] * adv[nt * 2 + 1];
            }
            #pragma unroll
            for (int o = 1; o <= 2; o <<= 1) {
                s0 += __shfl_xor_sync(0xffffffffu, s0, o);
                d0 += __shfl_xor_sync(0xffffffffu, d0, o);
                s1 += __shfl_xor_sync(0xffffffffu, s1, o);
                d1 += __shfl_xor_sync(0xffffffffu, d1, o);
            }
            if (c == 0) {
                int r0 = warpM + mt * 16 + g;
                atomicAdd(&sred[r0 * 2],           s0);
                atomicAdd(&sred[r0 * 2 + 1],       d0);
                atomicAdd(&sred[(r0 + 8) * 2],     s1);
                atomicAdd(&sred[(r0 + 8) * 2 + 1], d1);
            }
        }
        __syncthreads();
        if (tid < ROWS) {
            int row = blockM + tid;
            if (row < M) {
                das[row * hstride + blockIdx.x] = sred[tid * 2];
                dad[row * hstride + blockIdx.x] = sred[tid * 2 + 1];
            }
        }
    }

    // ---- store C ----
    #pragma unroll
    for (int mt = 0; mt < MT; mt++)
        #pragma unroll
        for (int nt = 0; nt < 4; nt++) {
            int row0 = blockM + warpM + mt * 16 + g;
            int col  = blockN + warpN + nt * 8 + 2 * c;
            if (row0 < M)
                *(float2*)(C + (size_t)row0 * N + col) =
                    make_float2(acc[mt][nt][0], acc[mt][nt][1]);
            int row1 = row0 + 8;
            if (row1 < M)
                *(float2*)(C + (size_t)row1 * N + col) =
                    make_float2(acc[mt][nt][2], acc[mt][nt][3]);
        }
}

// ---------------- GAT aggregation (round-13 proven versions) ----------------
__device__ __forceinline__ void sAtomicMaxF(float* a, float v) {
    int* ai = (int*)a;
    int old = *ai;
    while (__int_as_float(old) < v) {
        int assumed = old;
        old = atomicCAS(ai, assumed, __float_as_int(v));
        if (old == assumed) break;
    }
}

__global__ __launch_bounds__(256)
void k_agg1(const float* __restrict__ bias) {
    int n = blockIdx.x;
    int s0 = d_off[n];
    int deg = d_off[n + 1] - s0;
    __shared__ float sm[H1H], sz[H1H], sad[H1H];
    int tid = threadIdx.x;
    if (tid < H1H) { sad[tid] = d_ad1[n * H1H + tid]; sm[tid] = -1e30f; sz[tid] = 0.f; }
    __syncthreads();
    for (int idx = tid; idx < deg * H1H; idx += 256) {
        int e = idx >> 3, hh = idx & 7;
        int src = d_csr[s0 + e];
        float v = d_as1[src * H1H + hh] + sad[hh];
        v = v > 0.f ? v : NEG * v;
        sAtomicMaxF(&sm[hh], v);
    }
    __syncthreads();
    for (int idx = tid; idx < deg * H1H; idx += 256) {
        int e = idx >> 3, hh = idx & 7;
        int src = d_csr[s0 + e];
        float v = d_as1[src * H1H + hh] + sad[hh];
        v = v > 0.f ? v : NEG * v;
        atomicAdd(&sz[hh], __expf(v - sm[hh]));
    }
    __syncthreads();
    int c0 = tid * 4;
    int hh = c0 >> 7;
    float m = sm[hh], invz = 1.f / sz[hh], ad = sad[hh];
    float4 acc = make_float4(0.f, 0.f, 0.f, 0.f);
    for (int e = 0; e < deg; e++) {
        int src = d_csr[s0 + e];
        float v = d_as1[src * H1H + hh] + ad;
        v = v > 0.f ? v : NEG * v;
        float al = __expf(v - m) * invz;
        float4 hv = *(const float4*)(d_h1 + (size_t)src * F1 + c0);
        acc.x += al * hv.x; acc.y += al * hv.y;
        acc.z += al * hv.z; acc.w += al * hv.w;
    }
    float4 bb = *(const float4*)(bias + c0);
    acc.x += bb.x; acc.y += bb.y; acc.z += bb.z; acc.w += bb.w;
    *(float4*)(d_g1 + (size_t)n * F1 + c0) = acc;
}

__global__ __launch_bounds__(128)
void k_agg2(const float* __restrict__ bias) {
    int n = blockIdx.x;
    int s0 = d_off[n];
    int deg = d_off[n + 1] - s0;
    __shared__ float sm, sz, sad;
    int tid = threadIdx.x;
    if (tid == 0) { sad = d_ad2[n]; sm = -1e30f; sz = 0.f; }
    __syncthreads();
    for (int e = tid; e < deg; e += 128) {
        float v = d_as2[d_csr[s0 + e]] + sad;
        v = v > 0.f ? v : NEG * v;
        sAtomicMaxF(&sm, v);
    }
    __syncthreads();
    for (int e = tid; e < deg; e += 128) {
        float v = d_as2[d_csr[s0 + e]] + sad;
        v = v > 0.f ? v : NEG * v;
        atomicAdd(&sz, __expf(v - sm));
    }
    __syncthreads();
    float m = sm, invz = 1.f / sz, ad = sad;
    float acc = 0.f;
    for (int e = 0; e < deg; e++) {
        int src = d_csr[s0 + e];
        float v = d_as2[src] + ad;
        v = v > 0.f ? v : NEG * v;
        acc += __expf(v - m) * invz * d_h2[(size_t)src * F2 + tid];
    }
    d_g2[(size_t)n * F2 + tid] = acc + bias[tid];
}

// ---------------- BatchNorm ------------------------------------------------
__global__ void bn_stats(const float* __restrict__ x, float* __restrict__ sum,
                         float* __restrict__ sq, int F) {
    int col = blockIdx.x * 128 + threadIdx.x;
    float s = 0.f, q = 0.f;
    for (int r = blockIdx.y; r < NN; r += gridDim.y) {
        float v = x[(size_t)r * F + col];
        s += v; q += v * v;
    }
    atomicAdd(&sum[col], s);
    atomicAdd(&sq[col], q);
}

__global__ void bn_final(const float* __restrict__ sum, const float* __restrict__ sq,
                         const float* __restrict__ gamma, const float* __restrict__ beta,
                         float* __restrict__ scale, float* __restrict__ shift, int F) {
    int c = blockIdx.x * blockDim.x + threadIdx.x;
    if (c < F) {
        float mu  = sum[c] * (1.f / NN);
        float var = sq[c] * (1.f / NN) - mu * mu;
        float sc  = gamma[c] * rsqrtf(var + BNEPS);
        scale[c] = sc;
        shift[c] = beta[c] - mu * sc;
    }
}

// ---------------- classifier head (fused BN2+ELU, 4 nodes/block) ------------
__global__ __launch_bounds__(256)
void k_classifier(const float* __restrict__ g2, const float* __restrict__ scale,
                  const float* __restrict__ shift,
                  const float* __restrict__ Wc1, const float* __restrict__ bc1,
                  const float* __restrict__ Wc2, const float* __restrict__ bc2,
                  float* __restrict__ out) {
    int sg = threadIdx.x >> 6;
    int t  = threadIdx.x & 63;
    int n  = blockIdx.x * 4 + sg;
    __shared__ float sx[4][128], sh[4][64];
    float v0 = g2[(size_t)n * F2 + t]      * scale[t]      + shift[t];
    float v1 = g2[(size_t)n * F2 + 64 + t] * scale[t + 64] + shift[t + 64];
    sx[sg][t]      = eluf(v0);
    sx[sg][t + 64] = eluf(v1);
    __syncthreads();
    float s = bc1[t];
    #pragma unroll 8
    for (int k = 0; k < 128; k++) s += sx[sg][k] * Wc1[k * 64 + t];
    sh[sg][t] = fmaxf(s, 0.f);
    __syncthreads();
    if (t < 2) {
        float o = bc2[t];
        #pragma unroll 8
        for (int k = 0; k < 64; k++) o += sh[sg][k] * Wc2[k * 2 + t];
        out[n * 2 + t] = o;
    }
}

// ---------------- launch ----------------------------------------------------
extern "C" void kernel_launch(void* const* d_in, const int* in_sizes, int n_in,
                              void* d_out, int out_size) {
    const float* x     = (const float*)d_in[0];
    const void*  ei    = d_in[1];
    const float* W1    = (const float*)d_in[2];
    const float* atts1 = (const float*)d_in[3];
    const float* attd1 = (const float*)d_in[4];
    const float* b1    = (const float*)d_in[5];
    const float* W2    = (const float*)d_in[6];
    const float* atts2 = (const float*)d_in[7];
    const float* attd2 = (const float*)d_in[8];
    const float* b2    = (const float*)d_in[9];
    const float* g1    = (const float*)d_in[10];
    const float* be1   = (const float*)d_in[11];
    const float* g2w   = (const float*)d_in[12];
    const float* be2   = (const float*)d_in[13];
    const float* Wc1   = (const float*)d_in[14];
    const float* bc1   = (const float*)d_in[15];
    const float* Wc2   = (const float*)d_in[16];
    const float* bc2   = (const float*)d_in[17];
    float*       out   = (float*)d_out;

    void *p_deg, *p_h1, *p_g2, *p_bsum, *p_bsq, *p_scale, *p_shift;
    void *p_as1, *p_ad1, *p_as2, *p_ad2, *p_h2, *p_g1;
    void *p_xs, *p_g1s, *p_w1t, *p_w2t;
    cudaGetSymbolAddress(&p_deg,   d_deg);
    cudaGetSymbolAddress(&p_h1,    d_h1);
    cudaGetSymbolAddress(&p_g1,    d_g1);
    cudaGetSymbolAddress(&p_h2,    d_h2);
    cudaGetSymbolAddress(&p_g2,    d_g2);
    cudaGetSymbolAddress(&p_bsum,  d_bsum);
    cudaGetSymbolAddress(&p_bsq,   d_bsq);
    cudaGetSymbolAddress(&p_scale, d_scale);
    cudaGetSymbolAddress(&p_shift, d_shift);
    cudaGetSymbolAddress(&p_as1,   d_as1);
    cudaGetSymbolAddress(&p_ad1,   d_ad1);
    cudaGetSymbolAddress(&p_as2,   d_as2);
    cudaGetSymbolAddress(&p_ad2,   d_ad2);
    cudaGetSymbolAddress(&p_xs,    d_xs);
    cudaGetSymbolAddress(&p_g1s,   d_g1s);
    cudaGetSymbolAddress(&p_w1t,   d_w1t);
    cudaGetSymbolAddress(&p_w2t,   d_w2t);

    const int SMEM_MT4 = 3 * (4 * 4096 + 16384);   // 98304
    const int SMEM_MT2 = 3 * (2 * 4096 + 16384);   // 73728
    cudaFuncSetAttribute(gemm_lm<4>, cudaFuncAttributeMaxDynamicSharedMemorySize, SMEM_MT4);
    cudaFuncSetAttribute(gemm_lm<2>, cudaFuncAttributeMaxDynamicSharedMemorySize, SMEM_MT2);

    // conversions + CSR build (gemm1 is launch #5 incl. memset for ncu)
    conv_x<<<(NN * (DIN / 2) + 255) / 256, 256>>>(x);                      // 1
    conv_wt<<<(F1 * (K1P / 2) + 255) / 256, 256>>>(W1, (unsigned*)p_w1t, DIN, F1); // 2
    conv_wt<<<(F2 * (K2P / 2) + 255) / 256, 256>>>(W2, (unsigned*)p_w2t, F1, F2);  // 3
    cudaMemsetAsync(p_deg, 0, NN * sizeof(int));                            // 4

    // ---- GAT layer 1: split-bf16 HMMA GEMM (fused attention dots) ----
    {
        dim3 grid(F1 / 128, (NN + 127) / 128);
        gemm_lm<4><<<grid, 256, SMEM_MT4>>>((const unsigned*)p_xs,          // 5
                                            (const unsigned*)p_w1t,
                                            (float*)p_h1, NN, F1, K1P,
                                            atts1, attd1,
                                            (float*)p_as1, (float*)p_ad1, H1H);
    }

    k_detect<<<1, 64>>>(ei);
    k_count<<<(ETOT + 255) / 256, 256>>>(ei);
    k_scan<<<1, 1024>>>();
    k_scatter<<<(ETOT + 255) / 256, 256>>>(ei);   // also zeroes BN1 accumulators

    k_agg1<<<NN, 256>>>(b1);

    // BN1 stats -> conv_g1 applies BN+ELU, writes split A', zeroes BN2 accs
    {
        dim3 grid(F1 / 128, 128);
        bn_stats<<<grid, 128>>>((const float*)p_g1, (float*)p_bsum, (float*)p_bsq, F1);
    }
    bn_final<<<F1 / 128, 128>>>((const float*)p_bsum, (const float*)p_bsq, g1, be1,
                                (float*)p_scale, (float*)p_shift, F1);
    conv_g1<<<(NN * (F1 / 2) + 255) / 256, 256>>>((const float*)p_scale,
                                                  (const float*)p_shift);

    // ---- GAT layer 2: split-bf16 HMMA GEMM, M=64 tiles for occupancy ----
    {
        dim3 grid(1, (NN + 63) / 64);
        gemm_lm<2><<<grid, 256, SMEM_MT2>>>((const unsigned*)p_g1s,
                                            (const unsigned*)p_w2t,
                                            (float*)p_h2, NN, F2, K2P,
                                            atts2, attd2,
                                            (float*)p_as2, (float*)p_ad2, 1);
    }
    k_agg2<<<NN, 128>>>(b2);

    // BN2 stats (apply fused into classifier)
    {
        dim3 grid(F2 / 128, 128);
        bn_stats<<<grid, 128>>>((const float*)p_g2, (float*)p_bsum, (float*)p_bsq, F2);
    }
    bn_final<<<1, 128>>>((const float*)p_bsum, (const float*)p_bsq, g2w, be2,
                         (float*)p_scale, (float*)p_shift, F2);

    // ---- classifier head (fused BN2+ELU, 4 nodes/block) ----
    k_classifier<<<NN / 4, 256>>>((const float*)p_g2, (const float*)p_scale,
                                  (const float*)p_shift, Wc1, bc1, Wc2, bc2, out);
}